// round 6
// baseline (speedup 1.0000x reference)
#include <cuda_runtime.h>
#include <math.h>

#define N 4096
#define NTHREADS 1024
#define NCTA_ROW 64
#define ISLICE (N / NCTA_ROW)   // 64 targets per CTA
#define NCHUNK 64
#define CHUNK 64

typedef unsigned long long u64;
typedef unsigned int u32;

__device__ u64   g_keys[2][N];
__device__ float g_rank[2][N];
__device__ float g_sum[2], g_sumsq[2], g_bce;
__device__ u32   g_cnt[2];
__device__ u32   g_cnt2;

// exact integer W(start,cnt) = cnt*N - sum(start..start+cnt-1)
__device__ __forceinline__ float Wf(int s, int c) {
    return (float)(c * N - (((2 * s + c - 1) * c) >> 1));
}

__device__ __forceinline__ float blockReduceSum(float v, float* scratch) {
#pragma unroll
    for (int o = 16; o; o >>= 1) v += __shfl_down_sync(0xffffffffu, v, o);
    int w = threadIdx.x >> 5, l = threadIdx.x & 31;
    __syncthreads();
    if (l == 0) scratch[w] = v;
    __syncthreads();
    if (w == 0) {
        float t = scratch[l];   // exactly 32 warps
#pragma unroll
        for (int o = 16; o; o >>= 1) t += __shfl_down_sync(0xffffffffu, t, o);
        if (l == 0) scratch[0] = t;
    }
    __syncthreads();
    return scratch[0];
}

// SMEM: keys u64[N]; bStart i[N]; bCnt i[N]; bSum f[N]; fStart i[N+1]; fS f[N];
//       cntArr i[64]; nb; red f[32]; who
#define SMEM_BYTES (N * 8 + (5 * N + 1) * 4 + 64 * 4 + 4 + 32 * 4 + 8 + 16)

__global__ __launch_bounds__(NTHREADS, 1)
void fusedKernel(const float* __restrict__ yhat,
                 const float* __restrict__ ytar,
                 float* __restrict__ out) {
    extern __shared__ u64 smemBase[];
    u64*   keys   = smemBase;                    // N
    int*   bStart = (int*)(keys + N);            // N
    int*   bCnt   = bStart + N;                  // N
    float* bSum   = (float*)(bCnt + N);          // N
    int*   fStart = (int*)(bSum + N);            // N+1
    float* fS     = (float*)(fStart + N + 1);    // N
    int*   cntArr = (int*)(fS + N);              // NCHUNK
    int*   nbPtr  = cntArr + NCHUNK;             // 1
    float* red    = (float*)(nbPtr + 1);         // 32
    u32*   shWho  = (u32*)(red + 32);            // 2

    float* fArr = (float*)bStart;   // counting-phase reuse (16KB): raw floats

    const int tid  = threadIdx.x;
    const int row  = blockIdx.x >> 6;
    const int slot = blockIdx.x & (NCTA_ROW - 1);
    const float* src = row ? ytar : yhat;

    // ================= Phase 1: rank-by-counting (all 128 CTAs) =============
    // Descending-stable position: pos(i) = #{j<i: v_j >= v_i} + #{j>=i: v_j > v_i}
    ((float4*)fArr)[tid] = ((const float4*)src)[tid];
    __syncthreads();

    {
        const int lane = tid & 31;
        const int p    = tid & 15;                 // 16 threads per target
        const int i    = slot * ISLICE + (tid >> 4);
        const float vi = fArr[i];
        const float4* qp = (const float4*)fArr;    // 1024 quads of 4 floats
        // Quads [0, 16*slot) are entirely below every i of this CTA (block-uniform).
        // Thread p owns quads Q = 16t + p.
        u32 c = 0;
        int t = 0;
#pragma unroll 4
        for (; t < slot; ++t) {                    // j < i region: count v_j >= v_i
            float4 a = qp[(t << 4) + p];
            c += (u32)(a.x >= vi) + (u32)(a.y >= vi)
               + (u32)(a.z >= vi) + (u32)(a.w >= vi);
        }
#pragma unroll 4
        for (; t < 64; ++t) {                      // rest: count v_j > v_i
            float4 a = qp[(t << 4) + p];
            c += (u32)(a.x > vi) + (u32)(a.y > vi)
               + (u32)(a.z > vi) + (u32)(a.w > vi);
        }
        // Midzone fixup: quads Q in [16*slot, Qs] contain elements j < i that were
        // counted with '>' but need '>=' -> add equality matches with j < i.
        {
            const int Qs = i >> 2;
            int Q = (slot << 4) + p;
            if (Q <= Qs) {
                float4 a = qp[Q];
                int j0 = Q << 2;
                c += (u32)((a.x == vi) & (j0 + 0 < i))
                   + (u32)((a.y == vi) & (j0 + 1 < i))
                   + (u32)((a.z == vi) & (j0 + 2 < i))
                   + (u32)((a.w == vi) & (j0 + 3 < i));
            }
        }
        u32 pos = __reduce_add_sync(0xFFFFu << (lane & 16), c);
        if (p == 0)
            g_keys[row][pos] = ((u64)__float_as_uint(vi) << 32) | (u32)i;
    }

    // arrival gate: last CTA of this row continues with PAV
    __threadfence();
    __syncthreads();
    if (tid == 0) shWho[0] = atomicAdd(&g_cnt[row], 1);
    __syncthreads();
    if (shWho[0] != NCTA_ROW - 1) return;
    __threadfence();   // acquire: other CTAs' g_keys writes

    // ================= Phase 2: PAV on sorted keys (1 CTA per row) ==========
    {
        const u64* gk = g_keys[row];
#pragma unroll
        for (int m = 0; m < 4; m++) {
            int i = tid + m * NTHREADS;
            keys[i] = gk[i];
        }
    }
    __syncthreads();

    // ---- Phase A: per-chunk PAV (nonincreasing fit of z_i = s_i - (N-i)) ----
    if (tid < NCHUNK) {
        const int cbase = tid * CHUNK;
        int myCnt = 0;
        float tS  = __uint_as_float((u32)(keys[cbase] >> 32));
        int   tC  = 1, tSt = cbase;
        float tNum = tS - (float)(N - cbase);
        for (int i = cbase + 1; i < cbase + CHUNK; ++i) {
            float s  = __uint_as_float((u32)(keys[i] >> 32));
            float cS = s;
            int   cC = 1, cSt = i;
            float cNum = s - (float)(N - i);
            while (tNum * (float)cC < cNum * (float)tC) {
                cS += tS; cC += tC; cSt = tSt;
                cNum = cS - Wf(cSt, cC);
                if (myCnt == 0) { tC = 0; break; }
                myCnt--;
                tSt = bStart[cbase + myCnt];
                tS  = bSum[cbase + myCnt];
                tC  = bCnt[cbase + myCnt];
                tNum = tS - Wf(tSt, tC);
            }
            if (tC > 0) {
                bStart[cbase + myCnt] = tSt; bSum[cbase + myCnt] = tS; bCnt[cbase + myCnt] = tC;
                myCnt++;
            }
            tS = cS; tC = cC; tSt = cSt; tNum = cNum;
        }
        bStart[cbase + myCnt] = tSt; bSum[cbase + myCnt] = tS; bCnt[cbase + myCnt] = tC;
        cntArr[tid] = myCnt + 1;
    }
    __syncthreads();

    // ---- Phase B: serial merge of chunk block lists (blocks as atoms) ----
    if (tid == 0) {
        int nb = 0;
        int   tSt = bStart[0], tC = bCnt[0];
        float tS  = bSum[0];
        float tNum = tS - Wf(tSt, tC);
        for (int c = 0; c < NCHUNK; ++c) {
            int m = cntArr[c];
            for (int b = (c == 0) ? 1 : 0; b < m; ++b) {
                int off = c * CHUNK + b;
                int   cSt = bStart[off], cC = bCnt[off];
                float cS  = bSum[off];
                float cNum = cS - Wf(cSt, cC);
                while (tNum * (float)cC < cNum * (float)tC) {
                    cS += tS; cC += tC; cSt = tSt;
                    cNum = cS - Wf(cSt, cC);
                    if (nb == 0) { tC = 0; break; }
                    nb--;
                    int pSt = fStart[nb];
                    tS  = fS[nb];
                    tC  = cSt - pSt;
                    tSt = pSt;
                    tNum = tS - Wf(tSt, tC);
                }
                if (tC > 0) { fStart[nb] = tSt; fS[nb] = tS; nb++; }
                tS = cS; tC = cC; tSt = cSt; tNum = cNum;
            }
        }
        fStart[nb] = tSt; fS[nb] = tS; nb++;
        fStart[nb] = N;
        *nbPtr = nb;
    }
    __syncthreads();

    const int nb = *nbPtr;

    // ---- per-block dual mean ----
    for (int b = tid; b < nb; b += NTHREADS) {
        int s0 = fStart[b], cc = fStart[b + 1] - s0;
        fS[b] = (fS[b] - Wf(s0, cc)) / (float)cc;
    }
    __syncthreads();

    // ---- expand + scatter; keep local copy; accumulate own-row sums ----
    float* rLocal = bSum;    // bSum free after Phase B
    float sR = 0.f, sR2 = 0.f;
    for (int i = tid; i < N; i += NTHREADS) {
        u64 kk = keys[i];
        float s = __uint_as_float((u32)(kk >> 32));
        int  id = (int)(kk & 0xFFFFFFFFu);
        int lo = 0, hi = nb - 1;
        while (lo < hi) {
            int mid = (lo + hi + 1) >> 1;
            if (fStart[mid] <= i) lo = mid; else hi = mid - 1;
        }
        float r = s - fS[lo] - 2048.5f;    // shift is Spearman-invariant
        g_rank[row][id] = r;
        rLocal[id] = r;
        sR  += r;
        sR2 += r * r;
    }
    float S  = blockReduceSum(sR, red);
    float S2 = blockReduceSum(sR2, red);

    float B = 0.f;
    if (row == 1) {
        float sb = 0.f;
        for (int i = tid; i < N; i += NTHREADS) {
            float x  = yhat[i];
            float yy = ytar[i];
            sb += fmaxf(x, 0.f) + log1pf(expf(-fabsf(x))) - x * yy;
        }
        B = blockReduceSum(sb, red);
    }
    if (tid == 0) {
        g_sum[row]   = S;
        g_sumsq[row] = S2;
        if (row == 1) g_bce = B;
    }

    // ================= Phase 3: last PAV CTA finishes ========================
    __threadfence();
    __syncthreads();
    if (tid == 0) shWho[1] = atomicAdd(&g_cnt2, 1);
    __syncthreads();
    if (shWho[1] != 1) return;
    __threadfence();

    {
        const float* other = g_rank[1 - row];
        float cr = 0.f;
        for (int i = tid; i < N; i += NTHREADS)
            cr += other[i] * rLocal[i];
        cr = blockReduceSum(cr, red);
        if (tid == 0) {
            float invN = 1.0f / (float)N;
            float mp = g_sum[0] * invN, mt = g_sum[1] * invN;
            float varP = g_sumsq[0] - (float)N * mp * mp;
            float varT = g_sumsq[1] - (float)N * mt * mt;
            float cov  = cr - (float)N * mp * mt;
            float sp   = cov * rsqrtf(varP * varT);
            out[0] = (1.0f - sp) + g_bce * invN;
            g_cnt[0] = 0; g_cnt[1] = 0; g_cnt2 = 0;   // reset for graph replay
        }
    }
}

extern "C" void kernel_launch(void* const* d_in, const int* in_sizes, int n_in,
                              void* d_out, int out_size) {
    const float* yhat = (const float*)d_in[0];
    const float* ytar = (const float*)d_in[1];
    float* out = (float*)d_out;
    cudaFuncSetAttribute(fusedKernel,
                         cudaFuncAttributeMaxDynamicSharedMemorySize, SMEM_BYTES);
    fusedKernel<<<2 * NCTA_ROW, NTHREADS, SMEM_BYTES>>>(yhat, ytar, out);
}